// round 2
// baseline (speedup 1.0000x reference)
#include <cuda_runtime.h>
#include <math.h>

#define Bn 8192
#define Hn 512
#define Kn 16
#define NT 64   // number of N-tiles in gemm2 (8192/128)

// Scratch (static device arrays: allocation-free per harness rules)
__device__ float g_h[Bn * Hn];        // 16 MB: h = tanh((v_p-0.5)@W1+b1)
__device__ float g_part[Bn * NT];     // 2 MB: per-(row, ntile) partial of -sum log p_k

// ---------------------------------------------------------------------------
// Copy v_passive (first 512 cols of each 1024-col row) into v_out
// ---------------------------------------------------------------------------
__global__ __launch_bounds__(256) void copy_passive(const float* __restrict__ v_in,
                                                    float* __restrict__ v_out) {
    int idx = blockIdx.x * 256 + threadIdx.x;      // over Bn * (Hn/4) float4s
    int b = idx >> 7;                              // Hn/4 = 128 float4 per row
    int j = idx & 127;
    const float4* s = reinterpret_cast<const float4*>(v_in) + (size_t)b * 256 + j;
    float4* d = reinterpret_cast<float4*>(v_out) + (size_t)b * 256 + j;
    *d = *s;
}

// ---------------------------------------------------------------------------
// GEMM1: g_h[8192x512] = tanh( (v_in[:, :512] - 0.5) @ W1 + b1 )
// 128x128 tile, BK=8, 256 threads, 8x8 per thread
// ---------------------------------------------------------------------------
__global__ __launch_bounds__(256, 2) void gemm1(const float* __restrict__ v_in,
                                                const float* __restrict__ W1,
                                                const float* __restrict__ b1) {
    const int BK = 8;
    __shared__ float As[BK][128];
    __shared__ float Bs[BK][128];
    int tid = threadIdx.x;
    int tx = tid & 15, ty = tid >> 4;
    int rowBase = blockIdx.y * 128;
    int colBase = blockIdx.x * 128;

    float acc[8][8];
#pragma unroll
    for (int i = 0; i < 8; i++)
#pragma unroll
        for (int j = 0; j < 8; j++) acc[i][j] = 0.f;

    int arow = tid >> 1;
    int ak = (tid & 1) << 2;
    int bk = tid >> 5;
    int bcol = (tid & 31) << 2;
    const float* Abase = v_in + (size_t)rowBase * 1024;   // row stride 2H = 1024

    for (int k0 = 0; k0 < Hn; k0 += BK) {
        float4 av = *reinterpret_cast<const float4*>(Abase + (size_t)arow * 1024 + k0 + ak);
        As[ak + 0][arow] = av.x - 0.5f;
        As[ak + 1][arow] = av.y - 0.5f;
        As[ak + 2][arow] = av.z - 0.5f;
        As[ak + 3][arow] = av.w - 0.5f;
        *reinterpret_cast<float4*>(&Bs[bk][bcol]) =
            *reinterpret_cast<const float4*>(W1 + (size_t)(k0 + bk) * Hn + colBase + bcol);
        __syncthreads();
#pragma unroll
        for (int k = 0; k < BK; k++) {
            float a[8], bb[8];
            *(float4*)&a[0]  = *(float4*)&As[k][ty * 8];
            *(float4*)&a[4]  = *(float4*)&As[k][ty * 8 + 4];
            *(float4*)&bb[0] = *(float4*)&Bs[k][tx * 8];
            *(float4*)&bb[4] = *(float4*)&Bs[k][tx * 8 + 4];
#pragma unroll
            for (int i = 0; i < 8; i++)
#pragma unroll
                for (int j = 0; j < 8; j++) acc[i][j] += a[i] * bb[j];
        }
        __syncthreads();
    }

    float bias[8];
#pragma unroll
    for (int j = 0; j < 8; j++) bias[j] = b1[colBase + tx * 8 + j];
#pragma unroll
    for (int i = 0; i < 8; i++) {
        float out[8];
#pragma unroll
        for (int j = 0; j < 8; j++) out[j] = tanhf(acc[i][j] + bias[j]);
        float* dst = g_h + (size_t)(rowBase + ty * 8 + i) * Hn + colBase + tx * 8;
        *(float4*)dst       = *(float4*)&out[0];
        *(float4*)(dst + 4) = *(float4*)&out[4];
    }
}

// ---------------------------------------------------------------------------
// GEMM2 fused: net = tanh(g_h @ W2 + b2), per-(b,h) softmax over 16 cols,
// spline evaluation -> v_out active half, and -sum log p_k partials.
// ---------------------------------------------------------------------------
__global__ __launch_bounds__(256, 2) void gemm2(const float* __restrict__ v_in,
                                                const float* __restrict__ W2,
                                                const float* __restrict__ b2,
                                                float* __restrict__ v_out) {
    const int BK = 8;
    __shared__ float As[BK][128];
    __shared__ float Bs[BK][128];
    __shared__ float tile[64][132];   // half-tile of tanh(net), padded stride

    int tid = threadIdx.x;
    int tx = tid & 15, ty = tid >> 4;
    int rowBase = blockIdx.y * 128;
    int colBase = blockIdx.x * 128;

    float acc[8][8];
#pragma unroll
    for (int i = 0; i < 8; i++)
#pragma unroll
        for (int j = 0; j < 8; j++) acc[i][j] = 0.f;

    int arow = tid >> 1;
    int ak = (tid & 1) << 2;
    int bk = tid >> 5;
    int bcol = (tid & 31) << 2;
    const float* Abase = g_h + (size_t)rowBase * Hn;

    for (int k0 = 0; k0 < Hn; k0 += BK) {
        float4 av = *reinterpret_cast<const float4*>(Abase + (size_t)arow * Hn + k0 + ak);
        As[ak + 0][arow] = av.x;
        As[ak + 1][arow] = av.y;
        As[ak + 2][arow] = av.z;
        As[ak + 3][arow] = av.w;
        *reinterpret_cast<float4*>(&Bs[bk][bcol]) =
            *reinterpret_cast<const float4*>(W2 + (size_t)(k0 + bk) * 8192 + colBase + bcol);
        __syncthreads();
#pragma unroll
        for (int k = 0; k < BK; k++) {
            float a[8], bb[8];
            *(float4*)&a[0]  = *(float4*)&As[k][ty * 8];
            *(float4*)&a[4]  = *(float4*)&As[k][ty * 8 + 4];
            *(float4*)&bb[0] = *(float4*)&Bs[k][tx * 8];
            *(float4*)&bb[4] = *(float4*)&Bs[k][tx * 8 + 4];
#pragma unroll
            for (int i = 0; i < 8; i++)
#pragma unroll
                for (int j = 0; j < 8; j++) acc[i][j] += a[i] * bb[j];
        }
        __syncthreads();
    }

    float bias[8];
#pragma unroll
    for (int j = 0; j < 8; j++) bias[j] = b2[colBase + tx * 8 + j];

    // Epilogue in two 64-row halves so the staging tile fits static smem.
    for (int half = 0; half < 2; half++) {
        __syncthreads();
        if ((ty >> 3) == half) {
            int r0 = (ty & 7) * 8;
#pragma unroll
            for (int i = 0; i < 8; i++)
#pragma unroll
                for (int j = 0; j < 8; j++)
                    tile[r0 + i][tx * 8 + j] = tanhf(acc[i][j] + bias[j]);
        }
        __syncthreads();

#pragma unroll
        for (int cc = 0; cc < 2; cc++) {
            int cell = tid + cc * 256;      // 512 cells = 64 rows x 8 groups
            int r = cell >> 3;
            int g = cell & 7;
            int bglob = rowBase + half * 64 + r;
            int hglob = (colBase >> 4) + g;

            float n[16];
#pragma unroll
            for (int c4 = 0; c4 < 4; c4++)
                *(float4*)&n[c4 * 4] = *(float4*)&tile[r][g * 16 + c4 * 4];

            // spline bin: k = clip(searchsorted_left(linspace, v) - 1, 0, 15)
            //           = clip(ceil(16v) - 1, 0, 15)  (exact, incl. knot hits)
            float v = v_in[(size_t)bglob * 1024 + 512 + hglob];
            int kk = (int)ceilf(v * 16.0f) - 1;
            kk = kk < 0 ? 0 : (kk > 15 ? 15 : kk);

            float m = n[0];
#pragma unroll
            for (int c = 1; c < 16; c++) m = fmaxf(m, n[c]);

            float s = 0.f, pre = 0.f, ek = 0.f, nk = 0.f;
#pragma unroll
            for (int c = 0; c < 16; c++) {
                float ec = expf(n[c] - m);
                s += ec;
                if (c < kk)  pre += ec;
                if (c == kk) { ek = ec; nk = n[c]; }
            }
            float inv = 1.0f / s;
            float p_k  = ek * inv;
            float y_lo = pre * inv;
            float alpha = (v - (float)kk * 0.0625f) * 16.0f;
            v_out[(size_t)bglob * 1024 + 512 + hglob] = y_lo + alpha * p_k;

            // -log p_k = m + log(s) - net[kk]; reduce the 8 groups of this row
            float nlp = logf(s) + m - nk;
            nlp += __shfl_down_sync(0xffffffffu, nlp, 4, 8);
            nlp += __shfl_down_sync(0xffffffffu, nlp, 2, 8);
            nlp += __shfl_down_sync(0xffffffffu, nlp, 1, 8);
            if (g == 0) g_part[(size_t)bglob * NT + blockIdx.x] = nlp;
        }
    }
}

// ---------------------------------------------------------------------------
// Final reduction: log_density_out[b] = log_density[b] + sum_t g_part[b][t]
// ---------------------------------------------------------------------------
__global__ __launch_bounds__(256) void reduce_log(const float* __restrict__ log_density,
                                                  float* __restrict__ out_log) {
    int b = blockIdx.x * 256 + threadIdx.x;
    if (b < Bn) {
        float s = log_density[b];
        const float4* p = reinterpret_cast<const float4*>(g_part + (size_t)b * NT);
#pragma unroll
        for (int t = 0; t < NT / 4; t++) {
            float4 x = p[t];
            s += x.x; s += x.y; s += x.z; s += x.w;
        }
        out_log[b] = s;
    }
}

// ---------------------------------------------------------------------------
extern "C" void kernel_launch(void* const* d_in, const int* in_sizes, int n_in,
                              void* d_out, int out_size) {
    const float* v_in        = (const float*)d_in[0];
    const float* log_density = (const float*)d_in[1];
    const float* W1          = (const float*)d_in[2];
    const float* b1          = (const float*)d_in[3];
    const float* W2          = (const float*)d_in[4];
    const float* b2          = (const float*)d_in[5];
    float* v_out   = (float*)d_out;
    float* log_out = (float*)d_out + (size_t)Bn * 1024;

    copy_passive<<<(Bn * (Hn / 4)) / 256, 256>>>(v_in, v_out);
    gemm1<<<dim3(Hn / 128, Bn / 128), 256>>>(v_in, W1, b1);
    gemm2<<<dim3(8192 / 128, Bn / 128), 256>>>(v_in, W2, b2, v_out);
    reduce_log<<<Bn / 256, 256>>>(log_density, log_out);
}

// round 5
// speedup vs baseline: 3.4014x; 3.4014x over previous
#include <cuda_runtime.h>
#include <math.h>
#include <stdint.h>

#define Bn 8192
#define Hn 512
#define NT 64            // one -sum log p partial per (row, 128-col ntile)

// Static scratch (allocation-free per harness rules)
__device__ float g_a1[Bn * Hn];        // 16 MB: (v_passive - 0.5), tf32-rounded
__device__ float g_h[Bn * Hn];         // 16 MB: tanh(a1@W1+b1), tf32-rounded
__device__ float g_W1t[512 * 512];     // 1 MB : W1^T [n][k], tf32-rounded
__device__ float g_W2t[8192 * 512];    // 16 MB: W2^T [n][k], tf32-rounded
__device__ float g_part[Bn * NT];      // 2 MB

// ---------------------------------------------------------------------------
__device__ __forceinline__ uint32_t f2tf32(float f) {
    uint32_t r;
    asm("cvt.rna.tf32.f32 %0, %1;" : "=r"(r) : "f"(f));
    return r;
}
__device__ __forceinline__ uint32_t smem_u32(const void* p) {
    uint32_t a;
    asm("{ .reg .u64 t; cvta.to.shared.u64 t, %1; cvt.u32.u64 %0, t; }" : "=r"(a) : "l"(p));
    return a;
}
__device__ __forceinline__ void cp_async16(uint32_t dst, const void* src) {
    asm volatile("cp.async.cg.shared.global [%0], [%1], 16;" :: "r"(dst), "l"(src));
}
__device__ __forceinline__ void cp_commit() { asm volatile("cp.async.commit_group;"); }
__device__ __forceinline__ void cp_wait1() { asm volatile("cp.async.wait_group 1;"); }

__device__ __forceinline__ void mma_tf32(float& c0, float& c1, float& c2, float& c3,
                                         uint32_t a0, uint32_t a1, uint32_t a2, uint32_t a3,
                                         uint32_t b0, uint32_t b1) {
    asm volatile(
        "mma.sync.aligned.m16n8k8.row.col.f32.tf32.tf32.f32 "
        "{%0,%1,%2,%3}, {%4,%5,%6,%7}, {%8,%9}, {%0,%1,%2,%3};"
        : "+f"(c0), "+f"(c1), "+f"(c2), "+f"(c3)
        : "r"(a0), "r"(a1), "r"(a2), "r"(a3), "r"(b0), "r"(b1));
}

// Stage layout: A [128 rows][36 floats], B [128 rows][36 floats] (stride-36 pad)
#define STAGE_FLOATS (128 * 36 * 2)
#define STAGE_BYTES  (STAGE_FLOATS * 4)          // 36864
#define DYN1 (1024 + 2 * STAGE_BYTES)            // gemm1
// gemm2 epilogue tile: 128 x (164 + seg pad) floats = 83968 B > 2 stages
#define TILE_FLOATS (128 * 164)
#define DYN2 (1024 + (2 * STAGE_BYTES > TILE_FLOATS * 4 ? 2 * STAGE_BYTES : TILE_FLOATS * 4))
#define TIDX(r, c) ((r) * 164 + (c) + (((c) >> 4) << 2))

extern __shared__ char dynsmem[];

// ---------------------------------------------------------------------------
__global__ __launch_bounds__(256) void copy_passive(const float* __restrict__ v_in,
                                                    float* __restrict__ v_out) {
    int idx = blockIdx.x * 256 + threadIdx.x;
    int b = idx >> 7, j = idx & 127;
    const float4* s = reinterpret_cast<const float4*>(v_in) + (size_t)b * 256 + j;
    float4* d = reinterpret_cast<float4*>(v_out) + (size_t)b * 256 + j;
    *d = *s;
}

__global__ __launch_bounds__(256) void prep_a1(const float* __restrict__ v_in) {
    int idx = blockIdx.x * 256 + threadIdx.x;     // over Bn*128 float4s
    int b = idx >> 7, j = idx & 127;
    float4 v = *(reinterpret_cast<const float4*>(v_in) + (size_t)b * 256 + j);
    float4 o;
    o.x = __uint_as_float(f2tf32(v.x - 0.5f));
    o.y = __uint_as_float(f2tf32(v.y - 0.5f));
    o.z = __uint_as_float(f2tf32(v.z - 0.5f));
    o.w = __uint_as_float(f2tf32(v.w - 0.5f));
    *(reinterpret_cast<float4*>(g_a1) + (size_t)b * 128 + j) = o;
}

// Transpose W [K][N] -> Wt [N][K], tf32-rounded. N = row length of W.
__global__ __launch_bounds__(256) void transposeW(const float* __restrict__ W,
                                                  float* __restrict__ Wt, int N) {
    __shared__ float t[32][33];
    int x = threadIdx.x & 31, y = threadIdx.x >> 5;
    int n0 = blockIdx.x * 32, k0 = blockIdx.y * 32;
#pragma unroll
    for (int i = 0; i < 32; i += 8)
        t[y + i][x] = W[(size_t)(k0 + y + i) * N + n0 + x];
    __syncthreads();
#pragma unroll
    for (int i = 0; i < 32; i += 8)
        Wt[(size_t)(n0 + y + i) * 512 + k0 + x] =
            __uint_as_float(f2tf32(t[x][y + i]));
}

// ---------------------------------------------------------------------------
// Shared mainloop macro: 128x128 tile, K=512 in 16 chunks of 32, 2-stage cp.async.
// A from aptr [.][512], B from bptr [.][512] (both K-major, tf32 bits).
// ---------------------------------------------------------------------------
#define MMA_MAINLOOP(aptr, bptr)                                                   \
    uint32_t raw = smem_u32(dynsmem);                                              \
    uint32_t dat = (raw + 1023u) & ~1023u;                                         \
    uint32_t delta = dat - raw;                                                    \
    int tid = threadIdx.x;                                                         \
    int w = tid >> 5, lane = tid & 31;                                             \
    int wr = w >> 2, wc = w & 3;                                                   \
    int rowBase = blockIdx.y * 128, colBase = blockIdx.x * 128;                    \
    const float* Abase = (aptr) + (size_t)rowBase * 512;                           \
    const float* Bbase = (bptr) + (size_t)colBase * 512;                           \
    float acc[4][4][4];                                                            \
    _Pragma("unroll") for (int i = 0; i < 4; i++)                                  \
        _Pragma("unroll") for (int j = 0; j < 4; j++)                              \
            _Pragma("unroll") for (int q = 0; q < 4; q++) acc[i][j][q] = 0.f;      \
    auto load_chunk = [&](int chunk, int s) {                                      \
        int k0 = chunk * 32;                                                       \
        uint32_t sb = dat + (uint32_t)s * STAGE_BYTES;                             \
        _Pragma("unroll") for (int j = 0; j < 8; j++) {                            \
            int idx = tid + j * 256;                                               \
            int row = (idx >> 3) & 127, f4 = idx & 7;                              \
            if (idx < 1024)                                                        \
                cp_async16(sb + (uint32_t)(row * 144 + f4 * 16),                   \
                           Abase + (size_t)row * 512 + k0 + f4 * 4);               \
            else                                                                   \
                cp_async16(sb + 18432u + (uint32_t)(row * 144 + f4 * 16),          \
                           Bbase + (size_t)row * 512 + k0 + f4 * 4);               \
        }                                                                          \
        cp_commit();                                                               \
    };                                                                             \
    load_chunk(0, 0);                                                              \
    load_chunk(1, 1);                                                              \
    int aRow = wr * 64 + (lane >> 2), aK = lane & 3;                               \
    int bRow = wc * 32 + (lane >> 2);                                              \
    for (int i = 0; i < 16; i++) {                                                 \
        int s = i & 1;                                                             \
        cp_wait1();                                                                \
        __syncthreads();                                                           \
        const uint32_t* As = (const uint32_t*)(dynsmem + delta + s * STAGE_BYTES); \
        const uint32_t* Bs = As + 128 * 36;                                        \
        _Pragma("unroll") for (int ks = 0; ks < 4; ks++) {                         \
            uint32_t af[4][4], bf[4][2];                                           \
            _Pragma("unroll") for (int mf = 0; mf < 4; mf++) {                     \
                int base = (aRow + mf * 16) * 36 + ks * 8 + aK;                    \
                af[mf][0] = As[base];                                              \
                af[mf][1] = As[base + 8 * 36];                                     \
                af[mf][2] = As[base + 4];                                          \
                af[mf][3] = As[base + 8 * 36 + 4];                                 \
            }                                                                      \
            _Pragma("unroll") for (int nf = 0; nf < 4; nf++) {                     \
                int base = (bRow + nf * 8) * 36 + ks * 8 + aK;                     \
                bf[nf][0] = Bs[base];                                              \
                bf[nf][1] = Bs[base + 4];                                          \
            }                                                                      \
            _Pragma("unroll") for (int mf = 0; mf < 4; mf++)                       \
                _Pragma("unroll") for (int nf = 0; nf < 4; nf++)                   \
                    mma_tf32(acc[mf][nf][0], acc[mf][nf][1],                       \
                             acc[mf][nf][2], acc[mf][nf][3],                       \
                             af[mf][0], af[mf][1], af[mf][2], af[mf][3],           \
                             bf[nf][0], bf[nf][1]);                                \
        }                                                                          \
        __syncthreads();                                                           \
        if (i + 2 < 16) load_chunk(i + 2, s);                                      \
        else cp_commit();                                                          \
    }

// ---------------------------------------------------------------------------
// GEMM1: g_h = tf32( tanh( g_a1 @ W1 + b1 ) ).  Grid (512/128=4, 64).
// ---------------------------------------------------------------------------
__global__ __launch_bounds__(256, 2) void gemm1(const float* __restrict__ b1) {
    MMA_MAINLOOP(g_a1, g_W1t)

#pragma unroll
    for (int mf = 0; mf < 4; mf++) {
#pragma unroll
        for (int nf = 0; nf < 4; nf++) {
            int R0 = wr * 64 + mf * 16 + (lane >> 2);
            int C0 = wc * 32 + nf * 8 + 2 * (lane & 3);
            float bias0 = b1[colBase + C0], bias1 = b1[colBase + C0 + 1];
            float2 lo, hi;
            lo.x = __uint_as_float(f2tf32(tanhf(acc[mf][nf][0] + bias0)));
            lo.y = __uint_as_float(f2tf32(tanhf(acc[mf][nf][1] + bias1)));
            hi.x = __uint_as_float(f2tf32(tanhf(acc[mf][nf][2] + bias0)));
            hi.y = __uint_as_float(f2tf32(tanhf(acc[mf][nf][3] + bias1)));
            *reinterpret_cast<float2*>(g_h + (size_t)(rowBase + R0) * 512 + colBase + C0) = lo;
            *reinterpret_cast<float2*>(g_h + (size_t)(rowBase + R0 + 8) * 512 + colBase + C0) = hi;
        }
    }
}

// ---------------------------------------------------------------------------
// GEMM2: net = tanh(g_h @ W2 + b2) fused with softmax/spline/log epilogue.
// Grid (8192/128=64, 64).
// ---------------------------------------------------------------------------
__global__ __launch_bounds__(256, 2) void gemm2(const float* __restrict__ v_in,
                                                const float* __restrict__ b2,
                                                float* __restrict__ v_out) {
    MMA_MAINLOOP(g_h, g_W2t)

    // Dump tanh(acc + bias) into swizzled smem tile
    __syncthreads();
    float* tile = (float*)(dynsmem + delta);
#pragma unroll
    for (int mf = 0; mf < 4; mf++) {
#pragma unroll
        for (int nf = 0; nf < 4; nf++) {
            int R0 = wr * 64 + mf * 16 + (lane >> 2);
            int C0 = wc * 32 + nf * 8 + 2 * (lane & 3);
            float bias0 = b2[colBase + C0], bias1 = b2[colBase + C0 + 1];
            tile[TIDX(R0, C0)]         = tanhf(acc[mf][nf][0] + bias0);
            tile[TIDX(R0, C0 + 1)]     = tanhf(acc[mf][nf][1] + bias1);
            tile[TIDX(R0 + 8, C0)]     = tanhf(acc[mf][nf][2] + bias0);
            tile[TIDX(R0 + 8, C0 + 1)] = tanhf(acc[mf][nf][3] + bias1);
        }
    }
    __syncthreads();

    // Per-(row, 16-col group) softmax + spline. 1024 cells over 256 threads.
    float nlp_acc[4];
#pragma unroll
    for (int jj = 0; jj < 4; jj++) {
        int cell = jj * 256 + tid;
        int r = cell >> 3, g = cell & 7;
        int bglob = rowBase + r;
        int hglob = blockIdx.x * 8 + g;

        float n[16];
#pragma unroll
        for (int c4 = 0; c4 < 4; c4++)
            *(float4*)&n[c4 * 4] = *(const float4*)&tile[TIDX(r, g * 16 + c4 * 4)];

        float v = v_in[(size_t)bglob * 1024 + 512 + hglob];
        int kk = (int)ceilf(v * 16.0f) - 1;
        kk = kk < 0 ? 0 : (kk > 15 ? 15 : kk);

        float m = n[0];
#pragma unroll
        for (int c = 1; c < 16; c++) m = fmaxf(m, n[c]);
        float ssum = 0.f, pre = 0.f, ek = 0.f, nk = 0.f;
#pragma unroll
        for (int c = 0; c < 16; c++) {
            float ec = __expf(n[c] - m);
            ssum += ec;
            if (c < kk)  pre += ec;
            if (c == kk) { ek = ec; nk = n[c]; }
        }
        float inv = 1.0f / ssum;
        float p_k  = ek * inv;
        float y_lo = pre * inv;
        float alpha = (v - (float)kk * 0.0625f) * 16.0f;
        v_out[(size_t)bglob * 1024 + 512 + hglob] = y_lo + alpha * p_k;
        nlp_acc[jj] = __logf(ssum) + m - nk;
    }
    // Reduce 8 group-partials per row (g = tid&7 lives in low lane bits)
#pragma unroll
    for (int jj = 0; jj < 4; jj++) {
        float nlp = nlp_acc[jj];
        nlp += __shfl_down_sync(0xffffffffu, nlp, 4, 8);
        nlp += __shfl_down_sync(0xffffffffu, nlp, 2, 8);
        nlp += __shfl_down_sync(0xffffffffu, nlp, 1, 8);
        int cell = jj * 256 + tid;
        if ((cell & 7) == 0)
            g_part[(size_t)(rowBase + (cell >> 3)) * NT + blockIdx.x] = nlp;
    }
}

// ---------------------------------------------------------------------------
__global__ __launch_bounds__(256) void reduce_log(const float* __restrict__ log_density,
                                                  float* __restrict__ out_log) {
    int b = blockIdx.x * 256 + threadIdx.x;
    if (b < Bn) {
        float s = log_density[b];
        const float4* p = reinterpret_cast<const float4*>(g_part + (size_t)b * NT);
#pragma unroll
        for (int t = 0; t < NT / 4; t++) {
            float4 x = p[t];
            s += x.x; s += x.y; s += x.z; s += x.w;
        }
        out_log[b] = s;
    }
}

// ---------------------------------------------------------------------------
extern "C" void kernel_launch(void* const* d_in, const int* in_sizes, int n_in,
                              void* d_out, int out_size) {
    const float* v_in        = (const float*)d_in[0];
    const float* log_density = (const float*)d_in[1];
    const float* W1          = (const float*)d_in[2];
    const float* b1          = (const float*)d_in[3];
    const float* W2          = (const float*)d_in[4];
    const float* b2          = (const float*)d_in[5];
    float* v_out   = (float*)d_out;
    float* log_out = (float*)d_out + (size_t)Bn * 1024;

    cudaFuncSetAttribute(gemm1, cudaFuncAttributeMaxDynamicSharedMemorySize, DYN1);
    cudaFuncSetAttribute(gemm2, cudaFuncAttributeMaxDynamicSharedMemorySize, DYN2);

    copy_passive<<<(Bn * 128) / 256, 256>>>(v_in, v_out);
    prep_a1<<<(Bn * 128) / 256, 256>>>(v_in);
    float* w1t = nullptr; float* w2t = nullptr;
    cudaGetSymbolAddress((void**)&w1t, g_W1t);
    cudaGetSymbolAddress((void**)&w2t, g_W2t);
    transposeW<<<dim3(512 / 32, 512 / 32), 256>>>(W1, w1t, 512);
    transposeW<<<dim3(8192 / 32, 512 / 32), 256>>>(W2, w2t, 8192);
    gemm1<<<dim3(4, 64), 256, DYN1>>>(b1);
    gemm2<<<dim3(64, 64), 256, DYN2>>>(v_in, b2, v_out);
    reduce_log<<<Bn / 256, 256>>>(log_density, log_out);
}

// round 7
// speedup vs baseline: 5.8044x; 1.7065x over previous
#include <cuda_runtime.h>
#include <math.h>
#include <stdint.h>
#include <cuda_fp16.h>

#define Bn 8192
#define Hn 512
#define NT 64            // one -sum log p partial per (row, 128-col ntile)

// Static scratch (allocation-free per harness rules)
__device__ __half g_a1[Bn * Hn];        // 8 MB: (v_passive - 0.5) in fp16
__device__ __half g_h[Bn * Hn];         // 8 MB: tanh(a1@W1+b1) in fp16
__device__ __half g_W1t[512 * 512];     // 0.5 MB: W1^T [n][k] fp16
__device__ __half g_W2t[8192 * 512];    // 8 MB: W2^T [n][k] fp16
__device__ float  g_part[Bn * NT];      // 2 MB

// ---------------------------------------------------------------------------
__device__ __forceinline__ uint32_t smem_u32(const void* p) {
    uint32_t a;
    asm("{ .reg .u64 t; cvta.to.shared.u64 t, %1; cvt.u32.u64 %0, t; }" : "=r"(a) : "l"(p));
    return a;
}
__device__ __forceinline__ void cp_async16(uint32_t dst, const void* src) {
    asm volatile("cp.async.cg.shared.global [%0], [%1], 16;" :: "r"(dst), "l"(src));
}
__device__ __forceinline__ void cp_commit() { asm volatile("cp.async.commit_group;"); }
__device__ __forceinline__ void cp_wait1() { asm volatile("cp.async.wait_group 1;"); }

__device__ __forceinline__ void ldm_x4(uint32_t* r, uint32_t addr) {
    asm volatile("ldmatrix.sync.aligned.m8n8.x4.shared.b16 {%0,%1,%2,%3}, [%4];"
                 : "=r"(r[0]), "=r"(r[1]), "=r"(r[2]), "=r"(r[3]) : "r"(addr));
}
__device__ __forceinline__ void mma_f16(float& c0, float& c1, float& c2, float& c3,
                                        uint32_t a0, uint32_t a1, uint32_t a2, uint32_t a3,
                                        uint32_t b0, uint32_t b1) {
    asm volatile(
        "mma.sync.aligned.m16n8k16.row.col.f32.f16.f16.f32 "
        "{%0,%1,%2,%3}, {%4,%5,%6,%7}, {%8,%9}, {%0,%1,%2,%3};"
        : "+f"(c0), "+f"(c1), "+f"(c2), "+f"(c3)
        : "r"(a0), "r"(a1), "r"(a2), "r"(a3), "r"(b0), "r"(b1));
}

// Stage: A [128 rows][72 halves] + B [128 rows][72 halves], 144B pitch
// (pitch 144 = 9*16B: ldmatrix row-starts hit banks 4i mod 32 -> conflict-free)
#define ROW_PITCH 144
#define STAGE_BYTES (2 * 128 * ROW_PITCH)        // 36864
#define DYN1 (1024 + 2 * STAGE_BYTES)
#define TILE_FLOATS (128 * 164)
#define DYN2 (1024 + (2 * STAGE_BYTES > TILE_FLOATS * 4 ? 2 * STAGE_BYTES : TILE_FLOATS * 4))
#define TIDX(r, c) ((r) * 164 + (c) + (((c) >> 4) << 2))

extern __shared__ char dynsmem[];

// ---------------------------------------------------------------------------
__global__ __launch_bounds__(256) void copy_passive(const float* __restrict__ v_in,
                                                    float* __restrict__ v_out) {
    int idx = blockIdx.x * 256 + threadIdx.x;
    int b = idx >> 7, j = idx & 127;
    const float4* s = reinterpret_cast<const float4*>(v_in) + (size_t)b * 256 + j;
    float4* d = reinterpret_cast<float4*>(v_out) + (size_t)b * 256 + j;
    *d = *s;
}

// (v_passive - 0.5) -> fp16. Each thread: 8 floats -> 8 halves (16B store).
__global__ __launch_bounds__(256) void prep_a1(const float* __restrict__ v_in) {
    int idx = blockIdx.x * 256 + threadIdx.x;     // over Bn*64 groups of 8
    int b = idx >> 6, j = idx & 63;
    const float4* s = reinterpret_cast<const float4*>(v_in) + (size_t)b * 256 + j * 2;
    float4 v0 = s[0], v1 = s[1];
    __half2 o[4];
    o[0] = __floats2half2_rn(v0.x - 0.5f, v0.y - 0.5f);
    o[1] = __floats2half2_rn(v0.z - 0.5f, v0.w - 0.5f);
    o[2] = __floats2half2_rn(v1.x - 0.5f, v1.y - 0.5f);
    o[3] = __floats2half2_rn(v1.z - 0.5f, v1.w - 0.5f);
    *reinterpret_cast<float4*>(g_a1 + (size_t)b * 512 + j * 8) = *reinterpret_cast<float4*>(o);
}

// Transpose W [K][N] -> Wt [N][K] in fp16.
__global__ __launch_bounds__(256) void transposeW(const float* __restrict__ W,
                                                  __half* __restrict__ Wt, int N) {
    __shared__ float t[32][33];
    int x = threadIdx.x & 31, y = threadIdx.x >> 5;
    int n0 = blockIdx.x * 32, k0 = blockIdx.y * 32;
#pragma unroll
    for (int i = 0; i < 32; i += 8)
        t[y + i][x] = W[(size_t)(k0 + y + i) * N + n0 + x];
    __syncthreads();
#pragma unroll
    for (int i = 0; i < 32; i += 8)
        Wt[(size_t)(n0 + y + i) * 512 + k0 + x] = __float2half_rn(t[x][y + i]);
}

// ---------------------------------------------------------------------------
// Mainloop: 128x128 tile, K=512 in 8 chunks of 64 halves, 2-stage cp.async.
// 8 warps as 2x4: warp tile 64 rows x 32 cols. fp16 m16n8k16, ldmatrix frags.
// ---------------------------------------------------------------------------
#define MMA_MAINLOOP(aptr, bptr)                                                     \
    uint32_t raw = smem_u32(dynsmem);                                                \
    uint32_t dat = (raw + 1023u) & ~1023u;                                           \
    uint32_t delta = dat - raw;                                                      \
    int tid = threadIdx.x;                                                           \
    int w = tid >> 5, lane = tid & 31;                                               \
    int wr = w >> 2, wc = w & 3;                                                     \
    int rowBase = blockIdx.y * 128, colBase = blockIdx.x * 128;                      \
    const __half* Abase = (aptr) + (size_t)rowBase * 512;                            \
    const __half* Bbase = (bptr) + (size_t)colBase * 512;                            \
    float acc[4][4][4];                                                              \
    _Pragma("unroll") for (int i = 0; i < 4; i++)                                    \
        _Pragma("unroll") for (int j = 0; j < 4; j++)                                \
            _Pragma("unroll") for (int q = 0; q < 4; q++) acc[i][j][q] = 0.f;        \
    auto load_chunk = [&](int chunk, int s) {                                        \
        int k0 = chunk * 64;                                                         \
        uint32_t sb = dat + (uint32_t)s * STAGE_BYTES;                               \
        _Pragma("unroll") for (int j = 0; j < 8; j++) {                              \
            int idx = tid + j * 256;                                                 \
            int row = (idx >> 3) & 127, f4 = idx & 7;                                \
            if (idx < 1024)                                                          \
                cp_async16(sb + (uint32_t)(row * ROW_PITCH + f4 * 16),               \
                           Abase + (size_t)row * 512 + k0 + f4 * 8);                 \
            else                                                                     \
                cp_async16(sb + 18432u + (uint32_t)(row * ROW_PITCH + f4 * 16),      \
                           Bbase + (size_t)row * 512 + k0 + f4 * 8);                 \
        }                                                                            \
        cp_commit();                                                                 \
    };                                                                               \
    load_chunk(0, 0);                                                                \
    load_chunk(1, 1);                                                                \
    /* ldmatrix lane address bases (stage-relative) */                               \
    uint32_t aOff = (uint32_t)((wr * 64 + (lane & 15)) * ROW_PITCH + (lane >> 4) * 16); \
    uint32_t bOff = 18432u + (uint32_t)((wc * 32 + (lane & 7)) * ROW_PITCH + (lane >> 3) * 16); \
    for (int i = 0; i < NCHUNK; i++) {                                               \
        int s = i & 1;                                                               \
        cp_wait1();                                                                  \
        __syncthreads();                                                             \
        uint32_t stg = dat + (uint32_t)s * STAGE_BYTES;                              \
        uint32_t bfr[2][4][4];                                                       \
        _Pragma("unroll") for (int p = 0; p < 2; p++)                                \
            _Pragma("unroll") for (int nf = 0; nf < 4; nf++)                         \
                ldm_x4(bfr[p][nf], stg + bOff + (uint32_t)(nf * 8 * ROW_PITCH + p * 64)); \
        _Pragma("unroll") for (int ks = 0; ks < 4; ks++) {                           \
            uint32_t afr[4][4];                                                      \
            _Pragma("unroll") for (int mf = 0; mf < 4; mf++)                         \
                ldm_x4(afr[mf], stg + aOff + (uint32_t)(mf * 16 * ROW_PITCH + ks * 32)); \
            _Pragma("unroll") for (int mf = 0; mf < 4; mf++)                         \
                _Pragma("unroll") for (int nf = 0; nf < 4; nf++)                     \
                    mma_f16(acc[mf][nf][0], acc[mf][nf][1],                          \
                            acc[mf][nf][2], acc[mf][nf][3],                          \
                            afr[mf][0], afr[mf][1], afr[mf][2], afr[mf][3],          \
                            bfr[ks >> 1][nf][(ks & 1) * 2],                          \
                            bfr[ks >> 1][nf][(ks & 1) * 2 + 1]);                     \
        }                                                                            \
        __syncthreads();                                                             \
        if (i + 2 < NCHUNK) load_chunk(i + 2, s);                                    \
        else cp_commit();                                                            \
    }

#define NCHUNK 8

// ---------------------------------------------------------------------------
// GEMM1: g_h = fp16( tanh( g_a1 @ W1 + b1 ) ).  Grid (4, 64).
// ---------------------------------------------------------------------------
__global__ __launch_bounds__(256, 2) void gemm1(const float* __restrict__ b1) {
    MMA_MAINLOOP(g_a1, g_W1t)

#pragma unroll
    for (int mf = 0; mf < 4; mf++) {
#pragma unroll
        for (int nf = 0; nf < 4; nf++) {
            int R0 = wr * 64 + mf * 16 + (lane >> 2);
            int C0 = wc * 32 + nf * 8 + 2 * (lane & 3);
            float bias0 = b1[colBase + C0], bias1 = b1[colBase + C0 + 1];
            __half2 lo = __floats2half2_rn(tanhf(acc[mf][nf][0] + bias0),
                                           tanhf(acc[mf][nf][1] + bias1));
            __half2 hi = __floats2half2_rn(tanhf(acc[mf][nf][2] + bias0),
                                           tanhf(acc[mf][nf][3] + bias1));
            *reinterpret_cast<__half2*>(g_h + (size_t)(rowBase + R0) * 512 + colBase + C0) = lo;
            *reinterpret_cast<__half2*>(g_h + (size_t)(rowBase + R0 + 8) * 512 + colBase + C0) = hi;
        }
    }
}

// ---------------------------------------------------------------------------
// GEMM2: net = tanh(g_h @ W2 + b2) fused with softmax/spline/log epilogue.
// Grid (64, 64).
// ---------------------------------------------------------------------------
__global__ __launch_bounds__(256, 2) void gemm2(const float* __restrict__ v_in,
                                                const float* __restrict__ b2,
                                                float* __restrict__ v_out) {
    MMA_MAINLOOP(g_h, g_W2t)

    __syncthreads();
    float* tile = (float*)(dynsmem + delta);
#pragma unroll
    for (int mf = 0; mf < 4; mf++) {
#pragma unroll
        for (int nf = 0; nf < 4; nf++) {
            int R0 = wr * 64 + mf * 16 + (lane >> 2);
            int C0 = wc * 32 + nf * 8 + 2 * (lane & 3);
            float bias0 = b2[colBase + C0], bias1 = b2[colBase + C0 + 1];
            tile[TIDX(R0, C0)]         = tanhf(acc[mf][nf][0] + bias0);
            tile[TIDX(R0, C0 + 1)]     = tanhf(acc[mf][nf][1] + bias1);
            tile[TIDX(R0 + 8, C0)]     = tanhf(acc[mf][nf][2] + bias0);
            tile[TIDX(R0 + 8, C0 + 1)] = tanhf(acc[mf][nf][3] + bias1);
        }
    }
    __syncthreads();

    float nlp_acc[4];
#pragma unroll
    for (int jj = 0; jj < 4; jj++) {
        int cell = jj * 256 + tid;
        int r = cell >> 3, g = cell & 7;
        int bglob = rowBase + r;
        int hglob = blockIdx.x * 8 + g;

        float n[16];
#pragma unroll
        for (int c4 = 0; c4 < 4; c4++)
            *(float4*)&n[c4 * 4] = *(const float4*)&tile[TIDX(r, g * 16 + c4 * 4)];

        float v = v_in[(size_t)bglob * 1024 + 512 + hglob];
        int kk = (int)ceilf(v * 16.0f) - 1;
        kk = kk < 0 ? 0 : (kk > 15 ? 15 : kk);

        float m = n[0];
#pragma unroll
        for (int c = 1; c < 16; c++) m = fmaxf(m, n[c]);
        float ssum = 0.f, pre = 0.f, ek = 0.f, nk = 0.f;
#pragma unroll
        for (int c = 0; c < 16; c++) {
            float ec = __expf(n[c] - m);
            ssum += ec;
            if (c < kk)  pre += ec;
            if (c == kk) { ek = ec; nk = n[c]; }
        }
        float inv = 1.0f / ssum;
        float p_k  = ek * inv;
        float y_lo = pre * inv;
        float alpha = (v - (float)kk * 0.0625f) * 16.0f;
        v_out[(size_t)bglob * 1024 + 512 + hglob] = y_lo + alpha * p_k;
        nlp_acc[jj] = __logf(ssum) + m - nk;
    }
#pragma unroll
    for (int jj = 0; jj < 4; jj++) {
        float nlp = nlp_acc[jj];
        nlp += __shfl_down_sync(0xffffffffu, nlp, 4, 8);
        nlp += __shfl_down_sync(0xffffffffu, nlp, 2, 8);
        nlp += __shfl_down_sync(0xffffffffu, nlp, 1, 8);
        int cell = jj * 256 + tid;
        if ((cell & 7) == 0)
            g_part[(size_t)(rowBase + (cell >> 3)) * NT + blockIdx.x] = nlp;
    }
}

// ---------------------------------------------------------------------------
__global__ __launch_bounds__(256) void reduce_log(const float* __restrict__ log_density,
                                                  float* __restrict__ out_log) {
    int b = blockIdx.x * 256 + threadIdx.x;
    if (b < Bn) {
        float s = log_density[b];
        const float4* p = reinterpret_cast<const float4*>(g_part + (size_t)b * NT);
#pragma unroll
        for (int t = 0; t < NT / 4; t++) {
            float4 x = p[t];
            s += x.x; s += x.y; s += x.z; s += x.w;
        }
        out_log[b] = s;
    }
}

// ---------------------------------------------------------------------------
extern "C" void kernel_launch(void* const* d_in, const int* in_sizes, int n_in,
                              void* d_out, int out_size) {
    const float* v_in        = (const float*)d_in[0];
    const float* log_density = (const float*)d_in[1];
    const float* W1          = (const float*)d_in[2];
    const float* b1          = (const float*)d_in[3];
    const float* W2          = (const float*)d_in[4];
    const float* b2          = (const float*)d_in[5];
    float* v_out   = (float*)d_out;
    float* log_out = (float*)d_out + (size_t)Bn * 1024;

    cudaFuncSetAttribute(gemm1, cudaFuncAttributeMaxDynamicSharedMemorySize, DYN1);
    cudaFuncSetAttribute(gemm2, cudaFuncAttributeMaxDynamicSharedMemorySize, DYN2);

    copy_passive<<<(Bn * 128) / 256, 256>>>(v_in, v_out);
    prep_a1<<<(Bn * 64) / 256, 256>>>(v_in);
    __half* w1t = nullptr; __half* w2t = nullptr;
    cudaGetSymbolAddress((void**)&w1t, g_W1t);
    cudaGetSymbolAddress((void**)&w2t, g_W2t);
    transposeW<<<dim3(512 / 32, 512 / 32), 256>>>(W1, w1t, 512);
    transposeW<<<dim3(8192 / 32, 512 / 32), 256>>>(W2, w2t, 8192);
    gemm1<<<dim3(4, 64), 256, DYN1>>>(b1);
    gemm2<<<dim3(64, 64), 256, DYN2>>>(v_in, b2, v_out);
    reduce_log<<<Bn / 256, 256>>>(log_density, log_out);
}